// round 14
// baseline (speedup 1.0000x reference)
#include <cuda_runtime.h>
#include <cuda_bf16.h>

// Problem constants (fixed dataset): N=50000, E=800000, IN_F=256, OUT_F=64, HEADS=8
#define IN_F 256
#define OUT_F 64
#define MAXN 50000
#define MAXE 800000

// Static device scratch (no allocation allowed)
__device__ float g_hp[MAXN * OUT_F];      // projected features [N, 64]
__device__ int   g_counts[MAXN];          // in-degree histogram (invariant: 0 on entry)
__device__ int   g_offsets[MAXN + 1];     // CSR offsets by dst
__device__ int   g_rank[MAXE];            // edge's rank within its dst bucket
__device__ int   g_esrc[MAXE];            // src node id per edge, bucketed by dst

// Fused scan config
#define SCAN_T 256
#define SCAN_E 4
#define SCAN_CHUNK (SCAN_T * SCAN_E)                       // 1024 elems / block
#define SCAN_B ((MAXN + SCAN_CHUNK - 1) / SCAN_CHUNK)      // 49 blocks
__device__ int g_bsum[64];                                 // raw block totals
__device__ unsigned g_sbar;                                // monotonic ticket barrier

// Packed fp32x2 helpers (Blackwell sm_100+)
#define FMA_F32X2(d, a, b, c) \
    asm("fma.rn.f32x2 %0, %1, %2, %3;" : "=l"(d) : "l"(a), "l"(b), "l"(c))
#define PACK2(out, lo, hi) \
    asm("mov.b64 %0, {%1, %2};" : "=l"(out) : "f"(lo), "f"(hi))
#define UNPACK2(lo, hi, in) \
    asm("mov.b64 {%0, %1}, %2;" : "=f"(lo), "=f"(hi) : "l"(in))

// ---------------------------------------------------------------------------
// K1: histogram of dst + per-edge bucket rank (4 edges/thread).
// counts are zero on entry — re-zeroed by the fused scan.
// ---------------------------------------------------------------------------
__global__ void hist_kernel(const int* __restrict__ dst, int e) {
    int i4 = (blockIdx.x * blockDim.x + threadIdx.x) * 4;
    if (i4 + 3 < e) {
        int4 d = *(const int4*)&dst[i4];
        int4 r;
        r.x = atomicAdd(&g_counts[d.x], 1);
        r.y = atomicAdd(&g_counts[d.y], 1);
        r.z = atomicAdd(&g_counts[d.z], 1);
        r.w = atomicAdd(&g_counts[d.w], 1);
        *(int4*)&g_rank[i4] = r;
    } else {
        for (int i = i4; i < e; i++)
            g_rank[i] = atomicAdd(&g_counts[dst[i]], 1);
    }
}

// ---------------------------------------------------------------------------
// Grid barrier for the 49-block fused scan: monotonic ticket counter.
// ---------------------------------------------------------------------------
__device__ __forceinline__ void scan_barrier() {
    __syncthreads();
    if (threadIdx.x == 0) {
        __threadfence();
        unsigned t = atomicAdd(&g_sbar, 1u);
        unsigned target = (t / SCAN_B + 1u) * SCAN_B;
        while (*(volatile unsigned*)&g_sbar < target) __nanosleep(20);
    }
    __syncthreads();
}

// ---------------------------------------------------------------------------
// K2: FUSED scan (one launch, 49 all-resident blocks).
// ---------------------------------------------------------------------------
__global__ __launch_bounds__(SCAN_T)
void scan_fused_kernel(int n, int e) {
    __shared__ int warp_sums[SCAN_T / 32];
    int b    = blockIdx.x;
    int t    = threadIdx.x;
    int base = b * SCAN_CHUNK + t * SCAN_E;

    int v[SCAN_E];
#pragma unroll
    for (int i = 0; i < SCAN_E; i++)
        v[i] = (base + i < n) ? g_counts[base + i] : 0;

    int tsum = 0;
#pragma unroll
    for (int i = 0; i < SCAN_E; i++) tsum += v[i];

    int lane = t & 31, wid = t >> 5;
    int incl = tsum;
#pragma unroll
    for (int o = 1; o < 32; o <<= 1) {
        int x = __shfl_up_sync(0xFFFFFFFFu, incl, o);
        if (lane >= o) incl += x;
    }
    if (lane == 31) warp_sums[wid] = incl;
    __syncthreads();
    if (wid == 0) {
        int s = (lane < SCAN_T / 32) ? warp_sums[lane] : 0;
#pragma unroll
        for (int o = 1; o < SCAN_T / 32; o <<= 1) {
            int x = __shfl_up_sync(0xFFFFFFFFu, s, o);
            if (lane >= o) s += x;
        }
        if (lane < SCAN_T / 32) warp_sums[lane] = s;
    }
    __syncthreads();

    int texcl = (incl - tsum) + (wid > 0 ? warp_sums[wid - 1] : 0);

    if (t == SCAN_T - 1) g_bsum[b] = warp_sums[SCAN_T / 32 - 1];

    scan_barrier();

    __shared__ int red[64];
    if (t < 64) red[t] = (t < b && t < SCAN_B) ? __ldcg(&g_bsum[t]) : 0;
    __syncthreads();
#pragma unroll
    for (int o = 32; o > 0; o >>= 1) {
        if (t < o) red[t] += red[t + o];
        __syncthreads();
    }
    int boff = red[0];

    int run = boff + texcl;
#pragma unroll
    for (int i = 0; i < SCAN_E; i++) {
        int idx = base + i;
        if (idx < n) {
            g_offsets[idx] = run;
            g_counts[idx]  = 0;
            run += v[i];
        }
    }
    if (b == 0 && t == 0) g_offsets[n] = e;
}

// ---------------------------------------------------------------------------
// K3: ATOMIC-FREE scatter: p = offsets[dst] + rank (4 edges/thread).
// ---------------------------------------------------------------------------
__global__ void scatter_kernel(const int* __restrict__ src,
                               const int* __restrict__ dst, int e) {
    int i4 = (blockIdx.x * blockDim.x + threadIdx.x) * 4;
    if (i4 + 3 < e) {
        int4 s = *(const int4*)&src[i4];
        int4 d = *(const int4*)&dst[i4];
        int4 r = *(const int4*)&g_rank[i4];
        g_esrc[g_offsets[d.x] + r.x] = s.x;
        g_esrc[g_offsets[d.y] + r.y] = s.y;
        g_esrc[g_offsets[d.z] + r.z] = s.z;
        g_esrc[g_offsets[d.w] + r.w] = s.w;
    } else {
        for (int i = i4; i < e; i++)
            g_esrc[g_offsets[dst[i]] + g_rank[i]] = src[i];
    }
}

// ---------------------------------------------------------------------------
// K4: GEMM hp = h @ W — occupancy-tuned rework.
// 16-row x 64-col tile, 128 threads, 2 rows x 4 cols per thread.
// smem 16.6KB + launch_bounds(128,10) -> 10 blocks (40 warps)/SM.
// k-loop x4 with LDS.128 hv loads: per 4k = 2 LDS.128 + 4 LDG.128 + 8 PACK
// + 16 FFMA2 (0.94 issues/MAC, 3 L1 wavefronts/warp-k).
// ---------------------------------------------------------------------------
#define G_ROWS 16
#define G_THREADS 128
#define G_PITCH (IN_F + 4)

__global__ __launch_bounds__(G_THREADS, 10)
void gemm_kernel(const float* __restrict__ h, const float* __restrict__ W, int n) {
    __shared__ float sh[G_ROWS * G_PITCH];   // 16.6 KB

    int block_row = blockIdx.x * G_ROWS;

    // load 16x256 = 1024 float4; 128 threads -> 8 each
    for (int i = threadIdx.x; i < G_ROWS * (IN_F / 4); i += G_THREADS) {
        int r  = i / (IN_F / 4);
        int c4 = (i % (IN_F / 4)) * 4;
        float4 v = make_float4(0.f, 0.f, 0.f, 0.f);
        int gr = block_row + r;
        if (gr < n) v = *(const float4*)&h[(size_t)gr * IN_F + c4];
        *(float4*)&sh[r * G_PITCH + c4] = v;
    }
    __syncthreads();

    int tx = threadIdx.x & 15;   // 16 col groups of 4 cols
    int ty = threadIdx.x >> 4;   // 8 row groups of 2 rows
    int col  = tx * 4;
    int row0 = ty * 2;

    unsigned long long acc00 = 0ULL, acc01 = 0ULL, acc10 = 0ULL, acc11 = 0ULL;

#pragma unroll 2
    for (int k0 = 0; k0 < IN_F; k0 += 4) {
        float4 h0 = *(const float4*)&sh[(row0 + 0) * G_PITCH + k0];
        float4 h1 = *(const float4*)&sh[(row0 + 1) * G_PITCH + k0];
#pragma unroll
        for (int kk = 0; kk < 4; kk++) {
            ulonglong2 wv = *(const ulonglong2*)&W[(k0 + kk) * OUT_F + col];
            float e0 = (kk == 0) ? h0.x : (kk == 1) ? h0.y : (kk == 2) ? h0.z : h0.w;
            float e1 = (kk == 0) ? h1.x : (kk == 1) ? h1.y : (kk == 2) ? h1.z : h1.w;
            unsigned long long hv0, hv1;
            PACK2(hv0, e0, e0);
            PACK2(hv1, e1, e1);
            FMA_F32X2(acc00, hv0, wv.x, acc00);
            FMA_F32X2(acc01, hv0, wv.y, acc01);
            FMA_F32X2(acc10, hv1, wv.x, acc10);
            FMA_F32X2(acc11, hv1, wv.y, acc11);
        }
    }

    int gr0 = block_row + row0;
    if (gr0 < n) {
        float4 o;
        UNPACK2(o.x, o.y, acc00);
        UNPACK2(o.z, o.w, acc01);
        *(float4*)&g_hp[(size_t)gr0 * OUT_F + col] = o;
    }
    if (gr0 + 1 < n) {
        float4 o;
        UNPACK2(o.x, o.y, acc10);
        UNPACK2(o.z, o.w, acc11);
        *(float4*)&g_hp[(size_t)(gr0 + 1) * OUT_F + col] = o;
    }
}

// ---------------------------------------------------------------------------
// K5: warp-per-destination-node aggregation, 4-way edge ILP (float2 lanes).
// ---------------------------------------------------------------------------
__global__ __launch_bounds__(256)
void aggregate_kernel(const float* __restrict__ aw, int n_aw,
                      float* __restrict__ out, int n) {
    int warp = (blockIdx.x * blockDim.x + threadIdx.x) >> 5;
    int lane = threadIdx.x & 31;
    if (warp >= n) return;

    float c = 0.f;
    for (int i = 0; i < n_aw; i++) c += __ldg(&aw[i]);

    const float2* __restrict__ hp2 = (const float2*)g_hp;
    float2 hd = hp2[warp * 32 + lane];

    int beg = g_offsets[warp];
    int fin = g_offsets[warp + 1];

    float a0 = 0.f, a1 = 0.f;
    int e = beg;
    for (; e + 3 < fin; e += 4) {
        int s0 = g_esrc[e];
        int s1 = g_esrc[e + 1];
        int s2 = g_esrc[e + 2];
        int s3 = g_esrc[e + 3];
        float2 x0 = hp2[(size_t)s0 * 32 + lane];
        float2 x1 = hp2[(size_t)s1 * 32 + lane];
        float2 x2 = hp2[(size_t)s2 * 32 + lane];
        float2 x3 = hp2[(size_t)s3 * 32 + lane];
        float p0 = fmaf(x0.x, hd.x, x0.y * hd.y);
        float p1 = fmaf(x1.x, hd.x, x1.y * hd.y);
        float p2 = fmaf(x2.x, hd.x, x2.y * hd.y);
        float p3 = fmaf(x3.x, hd.x, x3.y * hd.y);
#pragma unroll
        for (int o = 16; o > 0; o >>= 1) {
            p0 += __shfl_xor_sync(0xFFFFFFFFu, p0, o);
            p1 += __shfl_xor_sync(0xFFFFFFFFu, p1, o);
            p2 += __shfl_xor_sync(0xFFFFFFFFu, p2, o);
            p3 += __shfl_xor_sync(0xFFFFFFFFu, p3, o);
        }
        a0 = fmaf(p0, x0.x, a0);
        a1 = fmaf(p0, x0.y, a1);
        a0 = fmaf(p1, x1.x, a0);
        a1 = fmaf(p1, x1.y, a1);
        a0 = fmaf(p2, x2.x, a0);
        a1 = fmaf(p2, x2.y, a1);
        a0 = fmaf(p3, x3.x, a0);
        a1 = fmaf(p3, x3.y, a1);
    }
    for (; e < fin; e++) {
        int s0 = g_esrc[e];
        float2 x = hp2[(size_t)s0 * 32 + lane];
        float p = fmaf(x.x, hd.x, x.y * hd.y);
#pragma unroll
        for (int o = 16; o > 0; o >>= 1)
            p += __shfl_xor_sync(0xFFFFFFFFu, p, o);
        a0 = fmaf(p, x.x, a0);
        a1 = fmaf(p, x.y, a1);
    }

    float2* out2 = (float2*)out;
    if (fin > beg) {
        out2[warp * 32 + lane] = make_float2(c * a0, c * a1);
    } else {
        out2[warp * 32 + lane] = hd;
    }
}

// ---------------------------------------------------------------------------
// Fork/join: GEMM on capture stream; CSR build chain on side stream.
// ---------------------------------------------------------------------------
extern "C" void kernel_launch(void* const* d_in, const int* in_sizes, int n_in,
                              void* d_out, int out_size) {
    const float* h   = (const float*)d_in[0];
    const float* W   = (const float*)d_in[1];
    const float* aw  = (const float*)d_in[2];
    const int*   src = (const int*)d_in[3];
    const int*   dst = (const int*)d_in[4];
    float* out = (float*)d_out;

    int n    = in_sizes[0] / IN_F;   // 50000
    int e    = in_sizes[3];          // 800000
    int n_aw = in_sizes[2];          // 8

    static cudaStream_t s2 = nullptr;
    static cudaEvent_t evFork = nullptr, evJoin = nullptr;
    if (s2 == nullptr) {
        cudaStreamCreateWithFlags(&s2, cudaStreamNonBlocking);
        cudaEventCreateWithFlags(&evFork, cudaEventDisableTiming);
        cudaEventCreateWithFlags(&evJoin, cudaEventDisableTiming);
    }

    int gemm_blocks = (n + G_ROWS - 1) / G_ROWS;

    cudaEventRecord(evFork, 0);
    cudaStreamWaitEvent(s2, evFork, 0);

    // Branch B (side stream): hist(+rank) -> fused scan -> atomic-free scatter
    hist_kernel<<<(e / 4 + 255) / 256, 256, 0, s2>>>(dst, e);
    scan_fused_kernel<<<SCAN_B, SCAN_T, 0, s2>>>(n, e);
    scatter_kernel<<<(e / 4 + 255) / 256, 256, 0, s2>>>(src, dst, e);
    cudaEventRecord(evJoin, s2);

    // Branch A (capture stream): GEMM
    gemm_kernel<<<gemm_blocks, G_THREADS>>>(h, W, n);

    // Join, then aggregate
    cudaStreamWaitEvent(0, evJoin, 0);
    aggregate_kernel<<<((n * 32) + 255) / 256, 256>>>(aw, n_aw, out, n);
}

// round 15
// speedup vs baseline: 1.2222x; 1.2222x over previous
#include <cuda_runtime.h>
#include <cuda_bf16.h>

// Problem constants (fixed dataset): N=50000, E=800000, IN_F=256, OUT_F=64, HEADS=8
#define IN_F 256
#define OUT_F 64
#define MAXN 50000
#define MAXE 800000

// Static device scratch (no allocation allowed)
__device__ float g_hp[MAXN * OUT_F];      // projected features [N, 64]
__device__ int   g_counts[MAXN];          // in-degree histogram (invariant: 0 on entry)
__device__ int   g_offsets[MAXN + 1];     // CSR offsets by dst
__device__ int   g_rank[MAXE];            // edge's rank within its dst bucket
__device__ int   g_esrc[MAXE];            // src node id per edge, bucketed by dst

// Fused scan config
#define SCAN_T 256
#define SCAN_E 4
#define SCAN_CHUNK (SCAN_T * SCAN_E)                       // 1024 elems / block
#define SCAN_B ((MAXN + SCAN_CHUNK - 1) / SCAN_CHUNK)      // 49 blocks
__device__ int g_bsum[64];                                 // raw block totals
__device__ unsigned g_sbar;                                // monotonic ticket barrier

// Packed fp32x2 helpers (Blackwell sm_100+)
#define FMA_F32X2(d, a, b, c) \
    asm("fma.rn.f32x2 %0, %1, %2, %3;" : "=l"(d) : "l"(a), "l"(b), "l"(c))
#define PACK2(out, lo, hi) \
    asm("mov.b64 %0, {%1, %2};" : "=l"(out) : "f"(lo), "f"(hi))
#define UNPACK2(lo, hi, in) \
    asm("mov.b64 {%0, %1}, %2;" : "=f"(lo), "=f"(hi) : "l"(in))

// ---------------------------------------------------------------------------
// K1: histogram of dst + per-edge bucket rank (4 edges/thread).
// counts are zero on entry — re-zeroed by the fused scan.
// ---------------------------------------------------------------------------
__global__ void hist_kernel(const int* __restrict__ dst, int e) {
    int i4 = (blockIdx.x * blockDim.x + threadIdx.x) * 4;
    if (i4 + 3 < e) {
        int4 d = *(const int4*)&dst[i4];
        int4 r;
        r.x = atomicAdd(&g_counts[d.x], 1);
        r.y = atomicAdd(&g_counts[d.y], 1);
        r.z = atomicAdd(&g_counts[d.z], 1);
        r.w = atomicAdd(&g_counts[d.w], 1);
        *(int4*)&g_rank[i4] = r;
    } else {
        for (int i = i4; i < e; i++)
            g_rank[i] = atomicAdd(&g_counts[dst[i]], 1);
    }
}

// ---------------------------------------------------------------------------
// Grid barrier for the 49-block fused scan: monotonic ticket counter.
// ---------------------------------------------------------------------------
__device__ __forceinline__ void scan_barrier() {
    __syncthreads();
    if (threadIdx.x == 0) {
        __threadfence();
        unsigned t = atomicAdd(&g_sbar, 1u);
        unsigned target = (t / SCAN_B + 1u) * SCAN_B;
        while (*(volatile unsigned*)&g_sbar < target) __nanosleep(20);
    }
    __syncthreads();
}

// ---------------------------------------------------------------------------
// K2: FUSED scan (one launch, 49 all-resident blocks).
// ---------------------------------------------------------------------------
__global__ __launch_bounds__(SCAN_T)
void scan_fused_kernel(int n, int e) {
    __shared__ int warp_sums[SCAN_T / 32];
    int b    = blockIdx.x;
    int t    = threadIdx.x;
    int base = b * SCAN_CHUNK + t * SCAN_E;

    int v[SCAN_E];
#pragma unroll
    for (int i = 0; i < SCAN_E; i++)
        v[i] = (base + i < n) ? g_counts[base + i] : 0;

    int tsum = 0;
#pragma unroll
    for (int i = 0; i < SCAN_E; i++) tsum += v[i];

    int lane = t & 31, wid = t >> 5;
    int incl = tsum;
#pragma unroll
    for (int o = 1; o < 32; o <<= 1) {
        int x = __shfl_up_sync(0xFFFFFFFFu, incl, o);
        if (lane >= o) incl += x;
    }
    if (lane == 31) warp_sums[wid] = incl;
    __syncthreads();
    if (wid == 0) {
        int s = (lane < SCAN_T / 32) ? warp_sums[lane] : 0;
#pragma unroll
        for (int o = 1; o < SCAN_T / 32; o <<= 1) {
            int x = __shfl_up_sync(0xFFFFFFFFu, s, o);
            if (lane >= o) s += x;
        }
        if (lane < SCAN_T / 32) warp_sums[lane] = s;
    }
    __syncthreads();

    int texcl = (incl - tsum) + (wid > 0 ? warp_sums[wid - 1] : 0);

    if (t == SCAN_T - 1) g_bsum[b] = warp_sums[SCAN_T / 32 - 1];

    scan_barrier();

    __shared__ int red[64];
    if (t < 64) red[t] = (t < b && t < SCAN_B) ? __ldcg(&g_bsum[t]) : 0;
    __syncthreads();
#pragma unroll
    for (int o = 32; o > 0; o >>= 1) {
        if (t < o) red[t] += red[t + o];
        __syncthreads();
    }
    int boff = red[0];

    int run = boff + texcl;
#pragma unroll
    for (int i = 0; i < SCAN_E; i++) {
        int idx = base + i;
        if (idx < n) {
            g_offsets[idx] = run;
            g_counts[idx]  = 0;
            run += v[i];
        }
    }
    if (b == 0 && t == 0) g_offsets[n] = e;
}

// ---------------------------------------------------------------------------
// K3: ATOMIC-FREE scatter: p = offsets[dst] + rank (4 edges/thread).
// ---------------------------------------------------------------------------
__global__ void scatter_kernel(const int* __restrict__ src,
                               const int* __restrict__ dst, int e) {
    int i4 = (blockIdx.x * blockDim.x + threadIdx.x) * 4;
    if (i4 + 3 < e) {
        int4 s = *(const int4*)&src[i4];
        int4 d = *(const int4*)&dst[i4];
        int4 r = *(const int4*)&g_rank[i4];
        g_esrc[g_offsets[d.x] + r.x] = s.x;
        g_esrc[g_offsets[d.y] + r.y] = s.y;
        g_esrc[g_offsets[d.z] + r.z] = s.z;
        g_esrc[g_offsets[d.w] + r.w] = s.w;
    } else {
        for (int i = i4; i < e; i++)
            g_esrc[g_offsets[dst[i]] + g_rank[i]] = src[i];
    }
}

// ---------------------------------------------------------------------------
// K4: GEMM hp = h @ W — R3 geometry (32-row tile, 4 rows x 4 cols/thread,
// 33KB smem, 6 blocks/SM) + k-unroll x4 with LDS.128 h loads.
// Per 4k per thread: 4 LDS.128 + 4 LDG.128(W) + 16 PACK + 32 FFMA2
// = 56 issues / 64 MACs; W load amortized over 16 MACs (L1-friendly).
// ---------------------------------------------------------------------------
#define G_ROWS 32
#define G_THREADS 128
#define G_PITCH (IN_F + 4)

__global__ __launch_bounds__(G_THREADS)
void gemm_kernel(const float* __restrict__ h, const float* __restrict__ W, int n) {
    __shared__ float sh[G_ROWS * G_PITCH];

    int block_row = blockIdx.x * G_ROWS;

    for (int i = threadIdx.x; i < G_ROWS * (IN_F / 4); i += G_THREADS) {
        int r  = i / (IN_F / 4);
        int c4 = (i % (IN_F / 4)) * 4;
        float4 v = make_float4(0.f, 0.f, 0.f, 0.f);
        int gr = block_row + r;
        if (gr < n) v = *(const float4*)&h[(size_t)gr * IN_F + c4];
        *(float4*)&sh[r * G_PITCH + c4] = v;
    }
    __syncthreads();

    int tx = threadIdx.x & 15;   // 16 col groups of 4 cols
    int ty = threadIdx.x >> 4;   // 8 row groups of 4 rows
    int col  = tx * 4;
    int row0 = ty * 4;

    unsigned long long acc2[4][2];
#pragma unroll
    for (int i = 0; i < 4; i++) { acc2[i][0] = 0ULL; acc2[i][1] = 0ULL; }

#pragma unroll 2
    for (int k0 = 0; k0 < IN_F; k0 += 4) {
        // 4 independent LDS.128: one 4-k slab per row
        float4 hr[4];
#pragma unroll
        for (int i = 0; i < 4; i++)
            hr[i] = *(const float4*)&sh[(row0 + i) * G_PITCH + k0];

#pragma unroll
        for (int kk = 0; kk < 4; kk++) {
            ulonglong2 wv = *(const ulonglong2*)&W[(k0 + kk) * OUT_F + col];
#pragma unroll
            for (int i = 0; i < 4; i++) {
                float e = (kk == 0) ? hr[i].x : (kk == 1) ? hr[i].y
                         : (kk == 2) ? hr[i].z : hr[i].w;
                unsigned long long hv2;
                PACK2(hv2, e, e);
                FMA_F32X2(acc2[i][0], hv2, wv.x, acc2[i][0]);
                FMA_F32X2(acc2[i][1], hv2, wv.y, acc2[i][1]);
            }
        }
    }

#pragma unroll
    for (int i = 0; i < 4; i++) {
        int gr = block_row + row0 + i;
        if (gr < n) {
            float4 o;
            UNPACK2(o.x, o.y, acc2[i][0]);
            UNPACK2(o.z, o.w, acc2[i][1]);
            *(float4*)&g_hp[(size_t)gr * OUT_F + col] = o;
        }
    }
}

// ---------------------------------------------------------------------------
// K5: warp-per-destination-node aggregation, 4-way edge ILP (float2 lanes).
// ---------------------------------------------------------------------------
__global__ __launch_bounds__(256)
void aggregate_kernel(const float* __restrict__ aw, int n_aw,
                      float* __restrict__ out, int n) {
    int warp = (blockIdx.x * blockDim.x + threadIdx.x) >> 5;
    int lane = threadIdx.x & 31;
    if (warp >= n) return;

    float c = 0.f;
    for (int i = 0; i < n_aw; i++) c += __ldg(&aw[i]);

    const float2* __restrict__ hp2 = (const float2*)g_hp;
    float2 hd = hp2[warp * 32 + lane];

    int beg = g_offsets[warp];
    int fin = g_offsets[warp + 1];

    float a0 = 0.f, a1 = 0.f;
    int e = beg;
    for (; e + 3 < fin; e += 4) {
        int s0 = g_esrc[e];
        int s1 = g_esrc[e + 1];
        int s2 = g_esrc[e + 2];
        int s3 = g_esrc[e + 3];
        float2 x0 = hp2[(size_t)s0 * 32 + lane];
        float2 x1 = hp2[(size_t)s1 * 32 + lane];
        float2 x2 = hp2[(size_t)s2 * 32 + lane];
        float2 x3 = hp2[(size_t)s3 * 32 + lane];
        float p0 = fmaf(x0.x, hd.x, x0.y * hd.y);
        float p1 = fmaf(x1.x, hd.x, x1.y * hd.y);
        float p2 = fmaf(x2.x, hd.x, x2.y * hd.y);
        float p3 = fmaf(x3.x, hd.x, x3.y * hd.y);
#pragma unroll
        for (int o = 16; o > 0; o >>= 1) {
            p0 += __shfl_xor_sync(0xFFFFFFFFu, p0, o);
            p1 += __shfl_xor_sync(0xFFFFFFFFu, p1, o);
            p2 += __shfl_xor_sync(0xFFFFFFFFu, p2, o);
            p3 += __shfl_xor_sync(0xFFFFFFFFu, p3, o);
        }
        a0 = fmaf(p0, x0.x, a0);
        a1 = fmaf(p0, x0.y, a1);
        a0 = fmaf(p1, x1.x, a0);
        a1 = fmaf(p1, x1.y, a1);
        a0 = fmaf(p2, x2.x, a0);
        a1 = fmaf(p2, x2.y, a1);
        a0 = fmaf(p3, x3.x, a0);
        a1 = fmaf(p3, x3.y, a1);
    }
    for (; e < fin; e++) {
        int s0 = g_esrc[e];
        float2 x = hp2[(size_t)s0 * 32 + lane];
        float p = fmaf(x.x, hd.x, x.y * hd.y);
#pragma unroll
        for (int o = 16; o > 0; o >>= 1)
            p += __shfl_xor_sync(0xFFFFFFFFu, p, o);
        a0 = fmaf(p, x.x, a0);
        a1 = fmaf(p, x.y, a1);
    }

    float2* out2 = (float2*)out;
    if (fin > beg) {
        out2[warp * 32 + lane] = make_float2(c * a0, c * a1);
    } else {
        out2[warp * 32 + lane] = hd;
    }
}

// ---------------------------------------------------------------------------
// Fork/join: GEMM on capture stream; CSR build chain on side stream.
// ---------------------------------------------------------------------------
extern "C" void kernel_launch(void* const* d_in, const int* in_sizes, int n_in,
                              void* d_out, int out_size) {
    const float* h   = (const float*)d_in[0];
    const float* W   = (const float*)d_in[1];
    const float* aw  = (const float*)d_in[2];
    const int*   src = (const int*)d_in[3];
    const int*   dst = (const int*)d_in[4];
    float* out = (float*)d_out;

    int n    = in_sizes[0] / IN_F;   // 50000
    int e    = in_sizes[3];          // 800000
    int n_aw = in_sizes[2];          // 8

    static cudaStream_t s2 = nullptr;
    static cudaEvent_t evFork = nullptr, evJoin = nullptr;
    if (s2 == nullptr) {
        cudaStreamCreateWithFlags(&s2, cudaStreamNonBlocking);
        cudaEventCreateWithFlags(&evFork, cudaEventDisableTiming);
        cudaEventCreateWithFlags(&evJoin, cudaEventDisableTiming);
    }

    int gemm_blocks = (n + G_ROWS - 1) / G_ROWS;

    cudaEventRecord(evFork, 0);
    cudaStreamWaitEvent(s2, evFork, 0);

    // Branch B (side stream): hist(+rank) -> fused scan -> atomic-free scatter
    hist_kernel<<<(e / 4 + 255) / 256, 256, 0, s2>>>(dst, e);
    scan_fused_kernel<<<SCAN_B, SCAN_T, 0, s2>>>(n, e);
    scatter_kernel<<<(e / 4 + 255) / 256, 256, 0, s2>>>(src, dst, e);
    cudaEventRecord(evJoin, s2);

    // Branch A (capture stream): GEMM
    gemm_kernel<<<gemm_blocks, G_THREADS>>>(h, W, n);

    // Join, then aggregate
    cudaStreamWaitEvent(0, evJoin, 0);
    aggregate_kernel<<<((n * 32) + 255) / 256, 256>>>(aw, n_aw, out, n);
}